// round 5
// baseline (speedup 1.0000x reference)
#include <cuda_runtime.h>
#include <cuda_bf16.h>
#include <cstdint>

// CausalConv1d as grouped GEMM on mma.sync bf16 (3-term hi/lo split emulating fp32).
// B=4, L=4096, D=2048, K=4, G=8.
// Per (b,g): C[4096,256] = A[4096,1024] x B[1024,256],
//   A[l, (ks,cin)] = x[b, l+ks-3, g*256+cin] (causal), B[(ks,cin), n] = w[ks, cin, g*256+n].
// R3: 523us (8 warps, 32x64 tiles) -- LDS floor == HMMA floor == 1536cyc/stage.
// R4: 569us FAILED (16 warps doubled B LDSM duplication -> crossbar-bound 2560cyc/stage).
// R5: revert to 8 warps; term-major MMA order (acc RAW distance 1->16), software-pipelined
//     fragments, warp tap-staggering, triple-buffered B + single barrier/stage.

#define B_ 4
#define L_ 4096
#define D_ 2048
#define CPG 256
#define TM 128
#define TN 128
#define NSTAGES 16     // 4 channel blocks x 4 taps
#define NTHREADS 256

// __device__ scratch: pre-split bf16 hi/lo copies of x and w.
__device__ __nv_bfloat16 g_xh[B_ * L_ * D_];
__device__ __nv_bfloat16 g_xl[B_ * L_ * D_];
__device__ __nv_bfloat16 g_wh[4 * 256 * D_];
__device__ __nv_bfloat16 g_wl[4 * 256 * D_];

// smem layout (bytes):
//  A: 2 bufs x [2 (h/l)][132 rows][128B]  (rows 131 used: l0-3 .. l0+127)
//  B: 3 bufs x [2 (h/l)][64 rows][256B]
#define A_HL 16896          // 132*128
#define A_BUF 33792         // 2*A_HL
#define OFF_B 67584         // 2*A_BUF
#define B_HL 16384          // 64*256
#define B_BUF 32768
#define SMEM_TOTAL (OFF_B + 3 * B_BUF)   // 165888

__device__ __forceinline__ uint32_t s2u(const void* p) {
    uint32_t a;
    asm("{ .reg .u64 t; cvta.to.shared.u64 t, %1; cvt.u32.u64 %0, t; }" : "=r"(a) : "l"(p));
    return a;
}

__device__ __forceinline__ void cp16(uint32_t dst, const void* src, uint32_t bytes) {
    asm volatile("cp.async.cg.shared.global [%0], [%1], 16, %2;"
                 :: "r"(dst), "l"(src), "r"(bytes));
}

#define LDSM4(r0, r1, r2, r3, a)                                                   \
    asm volatile("ldmatrix.sync.aligned.m8n8.x4.shared.b16 {%0,%1,%2,%3}, [%4];"   \
                 : "=r"(r0), "=r"(r1), "=r"(r2), "=r"(r3) : "r"(a))

#define LDSM4T(r0, r1, r2, r3, a)                                                       \
    asm volatile("ldmatrix.sync.aligned.m8n8.x4.trans.shared.b16 {%0,%1,%2,%3}, [%4];"  \
                 : "=r"(r0), "=r"(r1), "=r"(r2), "=r"(r3) : "r"(a))

#define MMA(d, a0, a1, a2, a3, b0, b1)                                             \
    asm volatile("mma.sync.aligned.m16n8k16.row.col.f32.bf16.bf16.f32 "            \
                 "{%0,%1,%2,%3},{%4,%5,%6,%7},{%8,%9},{%0,%1,%2,%3};"              \
                 : "+f"((d)[0]), "+f"((d)[1]), "+f"((d)[2]), "+f"((d)[3])          \
                 : "r"(a0), "r"(a1), "r"(a2), "r"(a3), "r"(b0), "r"(b1))

// Split fp32 pair -> packed bf16x2 hi and lo.
__device__ __forceinline__ void cvt_hl(float a, float b, uint32_t& hv, uint32_t& lv) {
    __nv_bfloat162 h = __floats2bfloat162_rn(a, b);
    uint32_t hb = *reinterpret_cast<uint32_t*>(&h);
    float ra = a - __uint_as_float(hb << 16);
    float rb = b - __uint_as_float(hb & 0xFFFF0000u);
    __nv_bfloat162 l = __floats2bfloat162_rn(ra, rb);
    hv = hb;
    lv = *reinterpret_cast<uint32_t*>(&l);
}

__global__ void __launch_bounds__(256) cvt_x_kernel(const float* __restrict__ x) {
    size_t i = (size_t)blockIdx.x * 256 + threadIdx.x;   // float4 index
    float4 v = reinterpret_cast<const float4*>(x)[i];
    uint32_t h0, l0, h1, l1;
    cvt_hl(v.x, v.y, h0, l0);
    cvt_hl(v.z, v.w, h1, l1);
    reinterpret_cast<uint2*>(g_xh)[i] = make_uint2(h0, h1);
    reinterpret_cast<uint2*>(g_xl)[i] = make_uint2(l0, l1);
}

__global__ void __launch_bounds__(256) cvt_w_kernel(const float* __restrict__ w) {
    size_t i = (size_t)blockIdx.x * 256 + threadIdx.x;
    float4 v = reinterpret_cast<const float4*>(w)[i];
    uint32_t h0, l0, h1, l1;
    cvt_hl(v.x, v.y, h0, l0);
    cvt_hl(v.z, v.w, h1, l1);
    reinterpret_cast<uint2*>(g_wh)[i] = make_uint2(h0, h1);
    reinterpret_cast<uint2*>(g_wl)[i] = make_uint2(l0, l1);
}

// ---- loaders (all 256 threads) ----
// A block: 131 rows (l0-3 .. l0+127) x 64 ch, hi+lo. chunks: 2*131*8 = 2096.
__device__ __forceinline__ void load_A(uint32_t smem_base, int abuf, int b, int l0,
                                       int gch0 /* gcol + cbase */) {
    const uint32_t base = smem_base + abuf * A_BUF;
    for (int idx = threadIdx.x; idx < 2096; idx += NTHREADS) {
        int hl  = idx >= 1048;
        int rem = hl ? idx - 1048 : idx;
        int row = rem >> 3;
        int c   = rem & 7;
        int l   = l0 - 3 + row;
        uint32_t bytes = (l >= 0) ? 16u : 0u;   // src-size 0 -> zero-fill (causal pad)
        int lc = l >= 0 ? l : 0;
        const __nv_bfloat16* src = (hl ? g_xl : g_xh) + ((size_t)(b * L_ + lc) * D_ + gch0 + c * 8);
        uint32_t dst = base + hl * A_HL + row * 128 + (((uint32_t)c ^ (row & 7)) << 4);
        cp16(dst, src, bytes);
    }
}

// B stage: 64 k-rows (cin) x 128 n, hi+lo. chunks: 2*64*16 = 2048.
__device__ __forceinline__ void load_B(uint32_t smem_base, int bbuf, int ks, int cbase,
                                       int ncol0 /* gcol + nt*128 */) {
    const uint32_t base = smem_base + OFF_B + bbuf * B_BUF;
    for (int idx = threadIdx.x; idx < 2048; idx += NTHREADS) {
        int hl  = idx >> 10;
        int rem = idx & 1023;
        int row = rem >> 4;
        int c   = rem & 15;
        const __nv_bfloat16* src =
            (hl ? g_wl : g_wh) + ((size_t)(ks * 256 + cbase + row) * D_ + ncol0 + c * 8);
        uint32_t dst = base + hl * B_HL + row * 256 + (((uint32_t)c ^ (row & 7)) << 4);
        cp16(dst, src, 16u);
    }
}

__global__ void __launch_bounds__(NTHREADS, 1)
cc1d_mma_kernel(float* __restrict__ out) {
    extern __shared__ char smem[];
    const uint32_t smem_base = s2u(smem);
    const int tid = threadIdx.x;
    const int wid = tid >> 5;
    const int lid = tid & 31;
    const int wm = wid & 3;      // warp row: 32 rows (4 m-warps)
    const int wn = wid >> 2;     // warp col: 64 cols (2 n-warps)
    // Tap stagger: warps on the same SMSP (wid, wid+4) process taps offset by 2.
    const int tstart = (wid >> 2) << 1;

    const int bid = blockIdx.x;
    const int nt = bid & 1;
    const int lt = (bid >> 1) & 31;
    const int g  = (bid >> 6) & 7;
    const int b  = bid >> 9;
    const int l0 = lt * TM;
    const int gcol = g * CPG;
    const int ncol0 = gcol + nt * TN;

    // ---- prologue: G0={A0,B0}, G1={B1} ----
    load_A(smem_base, 0, b, l0, gcol + 0);
    load_B(smem_base, 0, /*ks=*/0, /*cbase=*/0, ncol0);
    asm volatile("cp.async.commit_group;");
    load_B(smem_base, 1, /*ks=*/1, /*cbase=*/0, ncol0);
    asm volatile("cp.async.commit_group;");

    float acc[2][8][4];
#pragma unroll
    for (int u = 0; u < 2; ++u)
#pragma unroll
        for (int j = 0; j < 8; ++j)
#pragma unroll
            for (int q = 0; q < 4; ++q) acc[u][j][q] = 0.f;

    for (int s = 0; s < NSTAGES; ++s) {
        const int ks = s & 3;
        const uint32_t sA = smem_base + ((s >> 2) & 1) * A_BUF;
        const uint32_t sB = smem_base + OFF_B + (s % 3) * B_BUF;

        if (s == NSTAGES - 1) asm volatile("cp.async.wait_group 0;");
        else                  asm volatile("cp.async.wait_group 1;");
        __syncthreads();

        // Issue loads for stage s+2 right away (B (s+2)%3 free since stage s-1).
        if (s < NSTAGES - 2) {
            const int s2 = s + 2;
            if ((s2 & 3) == 0)
                load_A(smem_base, (s2 >> 2) & 1, b, l0, gcol + (s2 >> 2) * 64);
            load_B(smem_base, s2 % 3, s2 & 3, (s2 >> 2) * 64, ncol0);
            asm volatile("cp.async.commit_group;");
        }

        // Fragment regs: ah/bh double-buffered (pipelined one tap ahead),
        // al/bl single-buffered (loaded at iter top, used 1-2 terms later).
        uint32_t ah[2][2][4], bh[2][4][4];
        uint32_t al[2][4], bl[4][4];

        // Preload hi fragments for first tap.
        {
            int t = tstart;
#pragma unroll
            for (int u = 0; u < 2; ++u) {
                int row = wm * 32 + u * 16 + (lid & 15) + ks;
                int lc  = t * 2 + (lid >> 4);
                uint32_t addr = sA + row * 128 + (((uint32_t)lc ^ (row & 7)) << 4);
                LDSM4(ah[0][u][0], ah[0][u][1], ah[0][u][2], ah[0][u][3], addr);
            }
#pragma unroll
            for (int j2 = 0; j2 < 4; ++j2) {
                int row = t * 16 + (lid & 15);
                int lc  = wn * 8 + j2 * 2 + (lid >> 4);
                uint32_t addr = sB + row * 256 + (((uint32_t)lc ^ (row & 7)) << 4);
                LDSM4T(bh[0][j2][0], bh[0][j2][1], bh[0][j2][2], bh[0][j2][3], addr);
            }
        }

#pragma unroll
        for (int i = 0; i < 4; ++i) {
            const int cur = i & 1, nxt = cur ^ 1;
            const int t = (i + tstart) & 3;

            // Low fragments for current tap (first consumed one term later).
#pragma unroll
            for (int u = 0; u < 2; ++u) {
                int row = wm * 32 + u * 16 + (lid & 15) + ks;
                int lc  = t * 2 + (lid >> 4);
                uint32_t addr = sA + row * 128 + (((uint32_t)lc ^ (row & 7)) << 4) + A_HL;
                LDSM4(al[u][0], al[u][1], al[u][2], al[u][3], addr);
            }
#pragma unroll
            for (int j2 = 0; j2 < 4; ++j2) {
                int row = t * 16 + (lid & 15);
                int lc  = wn * 8 + j2 * 2 + (lid >> 4);
                uint32_t addr = sB + row * 256 + (((uint32_t)lc ^ (row & 7)) << 4) + B_HL;
                LDSM4T(bl[j2][0], bl[j2][1], bl[j2][2], bl[j2][3], addr);
            }
            // Hi fragments for next tap (overlaps with this tap's MMAs).
            if (i < 3) {
                int t2 = (i + 1 + tstart) & 3;
#pragma unroll
                for (int u = 0; u < 2; ++u) {
                    int row = wm * 32 + u * 16 + (lid & 15) + ks;
                    int lc  = t2 * 2 + (lid >> 4);
                    uint32_t addr = sA + row * 128 + (((uint32_t)lc ^ (row & 7)) << 4);
                    LDSM4(ah[nxt][u][0], ah[nxt][u][1], ah[nxt][u][2], ah[nxt][u][3], addr);
                }
#pragma unroll
                for (int j2 = 0; j2 < 4; ++j2) {
                    int row = t2 * 16 + (lid & 15);
                    int lc  = wn * 8 + j2 * 2 + (lid >> 4);
                    uint32_t addr = sB + row * 256 + (((uint32_t)lc ^ (row & 7)) << 4);
                    LDSM4T(bh[nxt][j2][0], bh[nxt][j2][1], bh[nxt][j2][2], bh[nxt][j2][3], addr);
                }
            }

            // Term-major MMAs: RAW distance on each acc = 16 MMAs.
#pragma unroll
            for (int u = 0; u < 2; ++u)
#pragma unroll
                for (int j = 0; j < 8; ++j) {
                    int j2 = j >> 1, o = (j & 1) * 2;
                    MMA(acc[u][j], ah[cur][u][0], ah[cur][u][1], ah[cur][u][2], ah[cur][u][3],
                        bh[cur][j2][o], bh[cur][j2][o + 1]);
                }
#pragma unroll
            for (int u = 0; u < 2; ++u)
#pragma unroll
                for (int j = 0; j < 8; ++j) {
                    int j2 = j >> 1, o = (j & 1) * 2;
                    MMA(acc[u][j], al[u][0], al[u][1], al[u][2], al[u][3],
                        bh[cur][j2][o], bh[cur][j2][o + 1]);
                }
#pragma unroll
            for (int u = 0; u < 2; ++u)
#pragma unroll
                for (int j = 0; j < 8; ++j) {
                    int j2 = j >> 1, o = (j & 1) * 2;
                    MMA(acc[u][j], ah[cur][u][0], ah[cur][u][1], ah[cur][u][2], ah[cur][u][3],
                        bl[j2][o], bl[j2][o + 1]);
                }
        }
    }

    // ---- epilogue: acc regs -> out ----
#pragma unroll
    for (int u = 0; u < 2; ++u)
#pragma unroll
        for (int j = 0; j < 8; ++j) {
            int m0 = wm * 32 + u * 16 + (lid >> 2);
            int n  = wn * 64 + j * 8 + (lid & 3) * 2;
            float* p = out + (size_t)(b * L_ + l0 + m0) * D_ + ncol0 + n;
            *reinterpret_cast<float2*>(p) = make_float2(acc[u][j][0], acc[u][j][1]);
            *reinterpret_cast<float2*>(p + 8 * D_) = make_float2(acc[u][j][2], acc[u][j][3]);
        }
}

extern "C" void kernel_launch(void* const* d_in, const int* in_sizes, int n_in,
                              void* d_out, int out_size) {
    const float* x = (const float*)d_in[0];   // [4, 4096, 2048] fp32
    const float* w = (const float*)d_in[1];   // [4, 256, 2048] fp32
    float* out = (float*)d_out;               // [4, 4096, 2048] fp32

    // pre-split fp32 -> bf16 hi/lo
    cvt_x_kernel<<<(B_ * L_ * D_ / 4) / 256, 256>>>(x);
    cvt_w_kernel<<<(4 * 256 * D_ / 4) / 256, 256>>>(w);

    cudaFuncSetAttribute(cc1d_mma_kernel, cudaFuncAttributeMaxDynamicSharedMemorySize, SMEM_TOTAL);
    // 2048 CTAs = 4 b x 8 g x 32 l-tiles x 2 n-tiles
    cc1d_mma_kernel<<<B_ * 8 * 32 * 2, NTHREADS, SMEM_TOTAL>>>(out);
}

// round 6
// speedup vs baseline: 1.5393x; 1.5393x over previous
#include <cuda_runtime.h>
#include <cuda_bf16.h>
#include <cstdint>

// CausalConv1d as grouped GEMM on mma.sync bf16 (3-term hi/lo split emulating fp32).
// B=4, L=4096, D=2048, K=4, G=8.
// Per (b,g): C[4096,256] = A[4096,1024] x B[1024,256],
//   A[l, (ks,cin)] = x[b, l+ks-3, g*256+cin] (causal), B[(ks,cin), n] = w[ks, cin, g*256+n].
// R3: 523us (8 warps, 32x64 warp tiles, 2-buf A, 2-buf B, 2 barriers/stage). BEST.
// R4: 569us FAILED (16 warps -> B-LDSM duplication, crossbar-bound).
// R5: 805us FAILED (frag double-buffering + stagger -> register spill).
// R6: R3 + ONE change: term-major MMA order (acc RAW distance 1 -> 16), register-neutral.

#define B_ 4
#define L_ 4096
#define D_ 2048
#define CPG 256
#define TM 128
#define TN 128
#define NSTAGES 16     // 4 channel blocks x 4 taps
#define NTHREADS 256

// __device__ scratch: pre-split bf16 hi/lo copies of x and w.
__device__ __nv_bfloat16 g_xh[B_ * L_ * D_];
__device__ __nv_bfloat16 g_xl[B_ * L_ * D_];
__device__ __nv_bfloat16 g_wh[4 * 256 * D_];
__device__ __nv_bfloat16 g_wl[4 * 256 * D_];

// smem layout (bytes):
//  A: 2 bufs x [2 (h/l)][132 rows][128B]  (rows 131 used: l0-3 .. l0+127)
//  B: 2 bufs x [2 (h/l)][64 rows][256B]
#define A_HL 16896          // 132*128
#define A_BUF 33792         // 2*A_HL
#define OFF_B 67584         // 2*A_BUF
#define B_HL 16384          // 64*256
#define B_BUF 32768
#define SMEM_TOTAL (OFF_B + 2 * B_BUF)   // 133120

__device__ __forceinline__ uint32_t s2u(const void* p) {
    uint32_t a;
    asm("{ .reg .u64 t; cvta.to.shared.u64 t, %1; cvt.u32.u64 %0, t; }" : "=r"(a) : "l"(p));
    return a;
}

__device__ __forceinline__ void cp16(uint32_t dst, const void* src, uint32_t bytes) {
    asm volatile("cp.async.cg.shared.global [%0], [%1], 16, %2;"
                 :: "r"(dst), "l"(src), "r"(bytes));
}

#define LDSM4(r0, r1, r2, r3, a)                                                   \
    asm volatile("ldmatrix.sync.aligned.m8n8.x4.shared.b16 {%0,%1,%2,%3}, [%4];"   \
                 : "=r"(r0), "=r"(r1), "=r"(r2), "=r"(r3) : "r"(a))

#define LDSM4T(r0, r1, r2, r3, a)                                                       \
    asm volatile("ldmatrix.sync.aligned.m8n8.x4.trans.shared.b16 {%0,%1,%2,%3}, [%4];"  \
                 : "=r"(r0), "=r"(r1), "=r"(r2), "=r"(r3) : "r"(a))

#define MMA(d, a0, a1, a2, a3, b0, b1)                                             \
    asm volatile("mma.sync.aligned.m16n8k16.row.col.f32.bf16.bf16.f32 "            \
                 "{%0,%1,%2,%3},{%4,%5,%6,%7},{%8,%9},{%0,%1,%2,%3};"              \
                 : "+f"((d)[0]), "+f"((d)[1]), "+f"((d)[2]), "+f"((d)[3])          \
                 : "r"(a0), "r"(a1), "r"(a2), "r"(a3), "r"(b0), "r"(b1))

// Split fp32 pair -> packed bf16x2 hi and lo.
__device__ __forceinline__ void cvt_hl(float a, float b, uint32_t& hv, uint32_t& lv) {
    __nv_bfloat162 h = __floats2bfloat162_rn(a, b);
    uint32_t hb = *reinterpret_cast<uint32_t*>(&h);
    float ra = a - __uint_as_float(hb << 16);
    float rb = b - __uint_as_float(hb & 0xFFFF0000u);
    __nv_bfloat162 l = __floats2bfloat162_rn(ra, rb);
    hv = hb;
    lv = *reinterpret_cast<uint32_t*>(&l);
}

__global__ void __launch_bounds__(256) cvt_x_kernel(const float* __restrict__ x) {
    size_t i = (size_t)blockIdx.x * 256 + threadIdx.x;   // float4 index
    float4 v = reinterpret_cast<const float4*>(x)[i];
    uint32_t h0, l0, h1, l1;
    cvt_hl(v.x, v.y, h0, l0);
    cvt_hl(v.z, v.w, h1, l1);
    reinterpret_cast<uint2*>(g_xh)[i] = make_uint2(h0, h1);
    reinterpret_cast<uint2*>(g_xl)[i] = make_uint2(l0, l1);
}

__global__ void __launch_bounds__(256) cvt_w_kernel(const float* __restrict__ w) {
    size_t i = (size_t)blockIdx.x * 256 + threadIdx.x;
    float4 v = reinterpret_cast<const float4*>(w)[i];
    uint32_t h0, l0, h1, l1;
    cvt_hl(v.x, v.y, h0, l0);
    cvt_hl(v.z, v.w, h1, l1);
    reinterpret_cast<uint2*>(g_wh)[i] = make_uint2(h0, h1);
    reinterpret_cast<uint2*>(g_wl)[i] = make_uint2(l0, l1);
}

// ---- loaders (all 256 threads) ----
// A block: 131 rows (l0-3 .. l0+127) x 64 ch, hi+lo. chunks: 2*131*8 = 2096.
__device__ __forceinline__ void load_A(uint32_t smem_base, int abuf, int b, int l0,
                                       int gch0 /* gcol + cbase */) {
    const uint32_t base = smem_base + abuf * A_BUF;
    for (int idx = threadIdx.x; idx < 2096; idx += NTHREADS) {
        int hl  = idx >= 1048;
        int rem = hl ? idx - 1048 : idx;
        int row = rem >> 3;
        int c   = rem & 7;
        int l   = l0 - 3 + row;
        uint32_t bytes = (l >= 0) ? 16u : 0u;   // src-size 0 -> zero-fill (causal pad)
        int lc = l >= 0 ? l : 0;
        const __nv_bfloat16* src = (hl ? g_xl : g_xh) + ((size_t)(b * L_ + lc) * D_ + gch0 + c * 8);
        uint32_t dst = base + hl * A_HL + row * 128 + (((uint32_t)c ^ (row & 7)) << 4);
        cp16(dst, src, bytes);
    }
}

// B stage: 64 k-rows (cin) x 128 n, hi+lo. chunks: 2*64*16 = 2048.
__device__ __forceinline__ void load_B(uint32_t smem_base, int bbuf, int ks, int cbase,
                                       int ncol0 /* gcol + nt*128 */) {
    const uint32_t base = smem_base + OFF_B + bbuf * B_BUF;
    for (int idx = threadIdx.x; idx < 2048; idx += NTHREADS) {
        int hl  = idx >> 10;
        int rem = idx & 1023;
        int row = rem >> 4;
        int c   = rem & 15;
        const __nv_bfloat16* src =
            (hl ? g_wl : g_wh) + ((size_t)(ks * 256 + cbase + row) * D_ + ncol0 + c * 8);
        uint32_t dst = base + hl * B_HL + row * 256 + (((uint32_t)c ^ (row & 7)) << 4);
        cp16(dst, src, 16u);
    }
}

__global__ void __launch_bounds__(NTHREADS, 1)
cc1d_mma_kernel(float* __restrict__ out) {
    extern __shared__ char smem[];
    const uint32_t smem_base = s2u(smem);
    const int tid = threadIdx.x;
    const int wid = tid >> 5;
    const int lid = tid & 31;
    const int wm = wid & 3;      // warp row: 32 rows
    const int wn = wid >> 2;     // warp col: 64 cols

    const int bid = blockIdx.x;
    const int nt = bid & 1;
    const int lt = (bid >> 1) & 31;
    const int g  = (bid >> 6) & 7;
    const int b  = bid >> 9;
    const int l0 = lt * TM;
    const int gcol = g * CPG;
    const int ncol0 = gcol + nt * TN;

    // ---- prologue ----
    load_A(smem_base, 0, b, l0, gcol + 0);
    load_B(smem_base, 0, /*ks=*/0, /*cbase=*/0, ncol0);
    asm volatile("cp.async.commit_group;");
    load_B(smem_base, 1, /*ks=*/1, /*cbase=*/0, ncol0);
    asm volatile("cp.async.commit_group;");

    float acc[2][8][4];
#pragma unroll
    for (int u = 0; u < 2; ++u)
#pragma unroll
        for (int j = 0; j < 8; ++j)
#pragma unroll
            for (int q = 0; q < 4; ++q) acc[u][j][q] = 0.f;

    for (int s = 0; s < NSTAGES; ++s) {
        const int ks = s & 3;
        const int abuf = (s >> 2) & 1;
        const int bbuf = s & 1;

        if (s == NSTAGES - 1) asm volatile("cp.async.wait_group 0;");
        else                  asm volatile("cp.async.wait_group 1;");
        __syncthreads();

        const uint32_t sA = smem_base + abuf * A_BUF;
        const uint32_t sB = smem_base + OFF_B + bbuf * B_BUF;

#pragma unroll
        for (int t = 0; t < 4; ++t) {
            uint32_t ah[2][4], al[2][4];
#pragma unroll
            for (int u = 0; u < 2; ++u) {
                int row = wm * 32 + u * 16 + (lid & 15) + ks;
                int lc  = t * 2 + (lid >> 4);
                uint32_t addr = sA + row * 128 + (((uint32_t)lc ^ (row & 7)) << 4);
                LDSM4(ah[u][0], ah[u][1], ah[u][2], ah[u][3], addr);
                LDSM4(al[u][0], al[u][1], al[u][2], al[u][3], addr + A_HL);
            }
            uint32_t bh[4][4], bl[4][4];
#pragma unroll
            for (int j2 = 0; j2 < 4; ++j2) {
                int row = t * 16 + (lid & 15);
                int lc  = wn * 8 + j2 * 2 + (lid >> 4);
                uint32_t addr = sB + row * 256 + (((uint32_t)lc ^ (row & 7)) << 4);
                LDSM4T(bh[j2][0], bh[j2][1], bh[j2][2], bh[j2][3], addr);
                LDSM4T(bl[j2][0], bl[j2][1], bl[j2][2], bl[j2][3], addr + B_HL);
            }
            // Term-major: RAW distance on each accumulator = 16 MMAs (was 1).
#pragma unroll
            for (int u = 0; u < 2; ++u)
#pragma unroll
                for (int j = 0; j < 8; ++j) {
                    int j2 = j >> 1, o = (j & 1) * 2;
                    MMA(acc[u][j], ah[u][0], ah[u][1], ah[u][2], ah[u][3],
                        bh[j2][o], bh[j2][o + 1]);
                }
#pragma unroll
            for (int u = 0; u < 2; ++u)
#pragma unroll
                for (int j = 0; j < 8; ++j) {
                    int j2 = j >> 1, o = (j & 1) * 2;
                    MMA(acc[u][j], al[u][0], al[u][1], al[u][2], al[u][3],
                        bh[j2][o], bh[j2][o + 1]);
                }
#pragma unroll
            for (int u = 0; u < 2; ++u)
#pragma unroll
                for (int j = 0; j < 8; ++j) {
                    int j2 = j >> 1, o = (j & 1) * 2;
                    MMA(acc[u][j], ah[u][0], ah[u][1], ah[u][2], ah[u][3],
                        bl[j2][o], bl[j2][o + 1]);
                }
        }

        if (s < NSTAGES - 2) {
            __syncthreads();   // all warps done with buffers about to be overwritten
            const int s2 = s + 2;
            if ((s2 & 3) == 0)
                load_A(smem_base, (s2 >> 2) & 1, b, l0, gcol + (s2 >> 2) * 64);
            load_B(smem_base, s2 & 1, s2 & 3, (s2 >> 2) * 64, ncol0);
            asm volatile("cp.async.commit_group;");
        }
    }

    // ---- epilogue: acc regs -> out ----
#pragma unroll
    for (int u = 0; u < 2; ++u)
#pragma unroll
        for (int j = 0; j < 8; ++j) {
            int m0 = wm * 32 + u * 16 + (lid >> 2);
            int n  = wn * 64 + j * 8 + (lid & 3) * 2;
            float* p = out + (size_t)(b * L_ + l0 + m0) * D_ + ncol0 + n;
            *reinterpret_cast<float2*>(p) = make_float2(acc[u][j][0], acc[u][j][1]);
            *reinterpret_cast<float2*>(p + 8 * D_) = make_float2(acc[u][j][2], acc[u][j][3]);
        }
}

extern "C" void kernel_launch(void* const* d_in, const int* in_sizes, int n_in,
                              void* d_out, int out_size) {
    const float* x = (const float*)d_in[0];   // [4, 4096, 2048] fp32
    const float* w = (const float*)d_in[1];   // [4, 256, 2048] fp32
    float* out = (float*)d_out;               // [4, 4096, 2048] fp32

    // pre-split fp32 -> bf16 hi/lo
    cvt_x_kernel<<<(B_ * L_ * D_ / 4) / 256, 256>>>(x);
    cvt_w_kernel<<<(4 * 256 * D_ / 4) / 256, 256>>>(w);

    cudaFuncSetAttribute(cc1d_mma_kernel, cudaFuncAttributeMaxDynamicSharedMemorySize, SMEM_TOTAL);
    // 2048 CTAs = 4 b x 8 g x 32 l-tiles x 2 n-tiles
    cc1d_mma_kernel<<<B_ * 8 * 32 * 2, NTHREADS, SMEM_TOTAL>>>(out);
}

// round 8
// speedup vs baseline: 3.7689x; 2.4484x over previous
#include <cuda_runtime.h>
#include <cuda_fp16.h>
#include <cstdint>

// CausalConv1d as grouped GEMM on mma.sync fp16 single-pass.
// B=4, L=4096, D=2048, K=4, G=8.
// Per (b,g): C[4096,256] = A[4096,1024] x B[1024,256],
//   A[l, (ks,cin)] = x[b, l+ks-3, g*256+cin] (causal), B[(ks,cin), n] = w[ks, cin, g*256+n].
// R3/R6: 523us bf16 3-term (rel_err 5.6e-6) -- HMMA-issue-bound (legacy path ~rt8).
// R7: single-pass fp16 (predicted rel_err ~3e-4 < 1e-3): 3x fewer HMMA, halved smem
//     -> 2 CTAs/SM. Structure otherwise identical to R3.

#define B_ 4
#define L_ 4096
#define D_ 2048
#define CPG 256
#define TM 128
#define TN 128
#define NSTAGES 16     // 4 channel blocks x 4 taps
#define NTHREADS 256

// __device__ scratch: pre-converted fp16 copies of x and w.
__device__ __half g_x16[B_ * L_ * D_];
__device__ __half g_w16[4 * 256 * D_];

// smem layout (bytes):
//  A: 2 bufs x [132 rows][128B]  (rows 131 used: l0-3 .. l0+127; 64ch x fp16)
//  B: 2 bufs x [64 rows][256B]   (128 n x fp16)
#define A_BUF 16896         // 132*128
#define OFF_B 33792         // 2*A_BUF
#define B_BUF 16384         // 64*256
#define SMEM_TOTAL (OFF_B + 2 * B_BUF)   // 66560 -> 2 CTAs/SM

__device__ __forceinline__ uint32_t s2u(const void* p) {
    uint32_t a;
    asm("{ .reg .u64 t; cvta.to.shared.u64 t, %1; cvt.u32.u64 %0, t; }" : "=r"(a) : "l"(p));
    return a;
}

__device__ __forceinline__ void cp16(uint32_t dst, const void* src, uint32_t bytes) {
    asm volatile("cp.async.cg.shared.global [%0], [%1], 16, %2;"
                 :: "r"(dst), "l"(src), "r"(bytes));
}

#define LDSM4(r0, r1, r2, r3, a)                                                   \
    asm volatile("ldmatrix.sync.aligned.m8n8.x4.shared.b16 {%0,%1,%2,%3}, [%4];"   \
                 : "=r"(r0), "=r"(r1), "=r"(r2), "=r"(r3) : "r"(a))

#define LDSM4T(r0, r1, r2, r3, a)                                                       \
    asm volatile("ldmatrix.sync.aligned.m8n8.x4.trans.shared.b16 {%0,%1,%2,%3}, [%4];"  \
                 : "=r"(r0), "=r"(r1), "=r"(r2), "=r"(r3) : "r"(a))

#define MMA(d, a0, a1, a2, a3, b0, b1)                                             \
    asm volatile("mma.sync.aligned.m16n8k16.row.col.f32.f16.f16.f32 "              \
                 "{%0,%1,%2,%3},{%4,%5,%6,%7},{%8,%9},{%0,%1,%2,%3};"              \
                 : "+f"((d)[0]), "+f"((d)[1]), "+f"((d)[2]), "+f"((d)[3])          \
                 : "r"(a0), "r"(a1), "r"(a2), "r"(a3), "r"(b0), "r"(b1))

__global__ void __launch_bounds__(256) cvt_x_kernel(const float* __restrict__ x) {
    size_t i = (size_t)blockIdx.x * 256 + threadIdx.x;   // float4 index
    float4 v = reinterpret_cast<const float4*>(x)[i];
    __half2 h0 = __floats2half2_rn(v.x, v.y);
    __half2 h1 = __floats2half2_rn(v.z, v.w);
    reinterpret_cast<uint2*>(g_x16)[i] =
        make_uint2(*reinterpret_cast<uint32_t*>(&h0), *reinterpret_cast<uint32_t*>(&h1));
}

__global__ void __launch_bounds__(256) cvt_w_kernel(const float* __restrict__ w) {
    size_t i = (size_t)blockIdx.x * 256 + threadIdx.x;
    float4 v = reinterpret_cast<const float4*>(w)[i];
    __half2 h0 = __floats2half2_rn(v.x, v.y);
    __half2 h1 = __floats2half2_rn(v.z, v.w);
    reinterpret_cast<uint2*>(g_w16)[i] =
        make_uint2(*reinterpret_cast<uint32_t*>(&h0), *reinterpret_cast<uint32_t*>(&h1));
}

// ---- loaders (all 256 threads) ----
// A block: 131 rows (l0-3 .. l0+127) x 64 ch fp16. chunks: 131*8 = 1048.
__device__ __forceinline__ void load_A(uint32_t smem_base, int abuf, int b, int l0,
                                       int gch0 /* gcol + cbase */) {
    const uint32_t base = smem_base + abuf * A_BUF;
    for (int idx = threadIdx.x; idx < 1048; idx += NTHREADS) {
        int row = idx >> 3;
        int c   = idx & 7;
        int l   = l0 - 3 + row;
        uint32_t bytes = (l >= 0) ? 16u : 0u;   // src-size 0 -> zero-fill (causal pad)
        int lc = l >= 0 ? l : 0;
        const __half* src = g_x16 + ((size_t)(b * L_ + lc) * D_ + gch0 + c * 8);
        uint32_t dst = base + row * 128 + (((uint32_t)c ^ (row & 7)) << 4);
        cp16(dst, src, bytes);
    }
}

// B stage: 64 k-rows (cin) x 128 n fp16. chunks: 64*16 = 1024.
__device__ __forceinline__ void load_B(uint32_t smem_base, int bbuf, int ks, int cbase,
                                       int ncol0 /* gcol + nt*128 */) {
    const uint32_t base = smem_base + OFF_B + bbuf * B_BUF;
    for (int idx = threadIdx.x; idx < 1024; idx += NTHREADS) {
        int row = idx >> 4;
        int c   = idx & 15;
        const __half* src = g_w16 + ((size_t)(ks * 256 + cbase + row) * D_ + ncol0 + c * 8);
        uint32_t dst = base + row * 256 + (((uint32_t)c ^ (row & 7)) << 4);
        cp16(dst, src, 16u);
    }
}

__global__ void __launch_bounds__(NTHREADS, 2)
cc1d_mma_kernel(float* __restrict__ out) {
    extern __shared__ char smem[];
    const uint32_t smem_base = s2u(smem);
    const int tid = threadIdx.x;
    const int wid = tid >> 5;
    const int lid = tid & 31;
    const int wm = wid & 3;      // warp row: 32 rows
    const int wn = wid >> 2;     // warp col: 64 cols

    const int bid = blockIdx.x;
    const int nt = bid & 1;
    const int lt = (bid >> 1) & 31;
    const int g  = (bid >> 6) & 7;
    const int b  = bid >> 9;
    const int l0 = lt * TM;
    const int gcol = g * CPG;
    const int ncol0 = gcol + nt * TN;

    // ---- prologue ----
    load_A(smem_base, 0, b, l0, gcol + 0);
    load_B(smem_base, 0, /*ks=*/0, /*cbase=*/0, ncol0);
    asm volatile("cp.async.commit_group;");
    load_B(smem_base, 1, /*ks=*/1, /*cbase=*/0, ncol0);
    asm volatile("cp.async.commit_group;");

    float acc[2][8][4];
#pragma unroll
    for (int u = 0; u < 2; ++u)
#pragma unroll
        for (int j = 0; j < 8; ++j)
#pragma unroll
            for (int q = 0; q < 4; ++q) acc[u][j][q] = 0.f;

    for (int s = 0; s < NSTAGES; ++s) {
        const int ks = s & 3;
        const int abuf = (s >> 2) & 1;
        const int bbuf = s & 1;

        if (s == NSTAGES - 1) asm volatile("cp.async.wait_group 0;");
        else                  asm volatile("cp.async.wait_group 1;");
        __syncthreads();

        const uint32_t sA = smem_base + abuf * A_BUF;
        const uint32_t sB = smem_base + OFF_B + bbuf * B_BUF;

#pragma unroll
        for (int t = 0; t < 4; ++t) {
            uint32_t ah[2][4];
#pragma unroll
            for (int u = 0; u < 2; ++u) {
                int row = wm * 32 + u * 16 + (lid & 15) + ks;
                int lc  = t * 2 + (lid >> 4);
                uint32_t addr = sA + row * 128 + (((uint32_t)lc ^ (row & 7)) << 4);
                LDSM4(ah[u][0], ah[u][1], ah[u][2], ah[u][3], addr);
            }
            uint32_t bh[4][4];
#pragma unroll
            for (int j2 = 0; j2 < 4; ++j2) {
                int row = t * 16 + (lid & 15);
                int lc  = wn * 8 + j2 * 2 + (lid >> 4);
                uint32_t addr = sB + row * 256 + (((uint32_t)lc ^ (row & 7)) << 4);
                LDSM4T(bh[j2][0], bh[j2][1], bh[j2][2], bh[j2][3], addr);
            }
#pragma unroll
            for (int u = 0; u < 2; ++u)
#pragma unroll
                for (int j = 0; j < 8; ++j) {
                    int j2 = j >> 1, o = (j & 1) * 2;
                    MMA(acc[u][j], ah[u][0], ah[u][1], ah[u][2], ah[u][3],
                        bh[j2][o], bh[j2][o + 1]);
                }
        }

        if (s < NSTAGES - 2) {
            __syncthreads();   // all warps done with buffers about to be overwritten
            const int s2 = s + 2;
            if ((s2 & 3) == 0)
                load_A(smem_base, (s2 >> 2) & 1, b, l0, gcol + (s2 >> 2) * 64);
            load_B(smem_base, s2 & 1, s2 & 3, (s2 >> 2) * 64, ncol0);
            asm volatile("cp.async.commit_group;");
        }
    }

    // ---- epilogue: acc regs -> out ----
#pragma unroll
    for (int u = 0; u < 2; ++u)
#pragma unroll
        for (int j = 0; j < 8; ++j) {
            int m0 = wm * 32 + u * 16 + (lid >> 2);
            int n  = wn * 64 + j * 8 + (lid & 3) * 2;
            float* p = out + (size_t)(b * L_ + l0 + m0) * D_ + ncol0 + n;
            *reinterpret_cast<float2*>(p) = make_float2(acc[u][j][0], acc[u][j][1]);
            *reinterpret_cast<float2*>(p + 8 * D_) = make_float2(acc[u][j][2], acc[u][j][3]);
        }
}

extern "C" void kernel_launch(void* const* d_in, const int* in_sizes, int n_in,
                              void* d_out, int out_size) {
    const float* x = (const float*)d_in[0];   // [4, 4096, 2048] fp32
    const float* w = (const float*)d_in[1];   // [4, 256, 2048] fp32
    float* out = (float*)d_out;               // [4, 4096, 2048] fp32

    // pre-convert fp32 -> fp16
    cvt_x_kernel<<<(B_ * L_ * D_ / 4) / 256, 256>>>(x);
    cvt_w_kernel<<<(4 * 256 * D_ / 4) / 256, 256>>>(w);

    cudaFuncSetAttribute(cc1d_mma_kernel, cudaFuncAttributeMaxDynamicSharedMemorySize, SMEM_TOTAL);
    // 2048 CTAs = 4 b x 8 g x 32 l-tiles x 2 n-tiles
    cc1d_mma_kernel<<<B_ * 8 * 32 * 2, NTHREADS, SMEM_TOTAL>>>(out);
}

// round 9
// speedup vs baseline: 3.7694x; 1.0001x over previous
#include <cuda_runtime.h>
#include <cuda_fp16.h>
#include <cstdint>

// CausalConv1d as grouped GEMM on mma.sync fp16 single-pass.
// B=4, L=4096, D=2048, K=4, G=8.
// Per (b,g): C[4096,256] = A[4096,1024] x B[1024,256],
//   A[l, (ks,cin)] = x[b, l+ks-3, g*256+cin] (causal), B[(ks,cin), n] = w[ks, cin, g*256+n].
// R3/R6: 523us bf16 3-term. R7: 213.5us fp16 single-pass (rel_err 2.9e-4), 2 CTAs/SM.
// R9: triple-buffer B -> single barrier/stage, loads issued right after barrier;
//     fused cvt kernel (1 launch; also shifts ncu -s5 onto the main kernel).

#define B_ 4
#define L_ 4096
#define D_ 2048
#define CPG 256
#define TM 128
#define TN 128
#define NSTAGES 16     // 4 channel blocks x 4 taps
#define NTHREADS 256

// __device__ scratch: pre-converted fp16 copies of x and w.
__device__ __half g_x16[B_ * L_ * D_];
__device__ __half g_w16[4 * 256 * D_];

#define NX4 (B_ * L_ * D_ / 4)        // 8388608 float4 units in x
#define NW4 (4 * 256 * D_ / 4)        // 524288 float4 units in w

// smem layout (bytes):
//  A: 2 bufs x [132 rows][128B]  (rows 131 used: l0-3 .. l0+127; 64ch x fp16)
//  B: 3 bufs x [64 rows][256B]   (128 n x fp16)
#define A_BUF 16896         // 132*128
#define OFF_B 33792         // 2*A_BUF
#define B_BUF 16384         // 64*256
#define SMEM_TOTAL (OFF_B + 3 * B_BUF)   // 82944 -> still 2 CTAs/SM

__device__ __forceinline__ uint32_t s2u(const void* p) {
    uint32_t a;
    asm("{ .reg .u64 t; cvta.to.shared.u64 t, %1; cvt.u32.u64 %0, t; }" : "=r"(a) : "l"(p));
    return a;
}

__device__ __forceinline__ void cp16(uint32_t dst, const void* src, uint32_t bytes) {
    asm volatile("cp.async.cg.shared.global [%0], [%1], 16, %2;"
                 :: "r"(dst), "l"(src), "r"(bytes));
}

#define LDSM4(r0, r1, r2, r3, a)                                                   \
    asm volatile("ldmatrix.sync.aligned.m8n8.x4.shared.b16 {%0,%1,%2,%3}, [%4];"   \
                 : "=r"(r0), "=r"(r1), "=r"(r2), "=r"(r3) : "r"(a))

#define LDSM4T(r0, r1, r2, r3, a)                                                       \
    asm volatile("ldmatrix.sync.aligned.m8n8.x4.trans.shared.b16 {%0,%1,%2,%3}, [%4];"  \
                 : "=r"(r0), "=r"(r1), "=r"(r2), "=r"(r3) : "r"(a))

#define MMA(d, a0, a1, a2, a3, b0, b1)                                             \
    asm volatile("mma.sync.aligned.m16n8k16.row.col.f32.f16.f16.f32 "              \
                 "{%0,%1,%2,%3},{%4,%5,%6,%7},{%8,%9},{%0,%1,%2,%3};"              \
                 : "+f"((d)[0]), "+f"((d)[1]), "+f"((d)[2]), "+f"((d)[3])          \
                 : "r"(a0), "r"(a1), "r"(a2), "r"(a3), "r"(b0), "r"(b1))

// Fused fp32 -> fp16 conversion for x and w (one launch).
__global__ void __launch_bounds__(256) cvt_kernel(const float* __restrict__ x,
                                                  const float* __restrict__ w) {
    size_t i = (size_t)blockIdx.x * 256 + threadIdx.x;
    const float4* src;
    uint2* dst;
    size_t j;
    if (i < NX4) { src = reinterpret_cast<const float4*>(x); dst = reinterpret_cast<uint2*>(g_x16); j = i; }
    else if (i < NX4 + NW4) { src = reinterpret_cast<const float4*>(w); dst = reinterpret_cast<uint2*>(g_w16); j = i - NX4; }
    else return;
    float4 v = src[j];
    __half2 h0 = __floats2half2_rn(v.x, v.y);
    __half2 h1 = __floats2half2_rn(v.z, v.w);
    dst[j] = make_uint2(*reinterpret_cast<uint32_t*>(&h0), *reinterpret_cast<uint32_t*>(&h1));
}

// ---- loaders (all 256 threads) ----
// A block: 131 rows (l0-3 .. l0+127) x 64 ch fp16. chunks: 131*8 = 1048.
__device__ __forceinline__ void load_A(uint32_t smem_base, int abuf, int b, int l0,
                                       int gch0 /* gcol + cbase */) {
    const uint32_t base = smem_base + abuf * A_BUF;
    for (int idx = threadIdx.x; idx < 1048; idx += NTHREADS) {
        int row = idx >> 3;
        int c   = idx & 7;
        int l   = l0 - 3 + row;
        uint32_t bytes = (l >= 0) ? 16u : 0u;   // src-size 0 -> zero-fill (causal pad)
        int lc = l >= 0 ? l : 0;
        const __half* src = g_x16 + ((size_t)(b * L_ + lc) * D_ + gch0 + c * 8);
        uint32_t dst = base + row * 128 + (((uint32_t)c ^ (row & 7)) << 4);
        cp16(dst, src, bytes);
    }
}

// B stage: 64 k-rows (cin) x 128 n fp16. chunks: 64*16 = 1024.
__device__ __forceinline__ void load_B(uint32_t smem_base, int bbuf, int ks, int cbase,
                                       int ncol0 /* gcol + nt*128 */) {
    const uint32_t base = smem_base + OFF_B + bbuf * B_BUF;
    for (int idx = threadIdx.x; idx < 1024; idx += NTHREADS) {
        int row = idx >> 4;
        int c   = idx & 15;
        const __half* src = g_w16 + ((size_t)(ks * 256 + cbase + row) * D_ + ncol0 + c * 8);
        uint32_t dst = base + row * 256 + (((uint32_t)c ^ (row & 7)) << 4);
        cp16(dst, src, 16u);
    }
}

__global__ void __launch_bounds__(NTHREADS, 2)
cc1d_mma_kernel(float* __restrict__ out) {
    extern __shared__ char smem[];
    const uint32_t smem_base = s2u(smem);
    const int tid = threadIdx.x;
    const int wid = tid >> 5;
    const int lid = tid & 31;
    const int wm = wid & 3;      // warp row: 32 rows
    const int wn = wid >> 2;     // warp col: 64 cols

    const int bid = blockIdx.x;
    const int nt = bid & 1;
    const int lt = (bid >> 1) & 31;
    const int g  = (bid >> 6) & 7;
    const int b  = bid >> 9;
    const int l0 = lt * TM;
    const int gcol = g * CPG;
    const int ncol0 = gcol + nt * TN;

    // ---- prologue: G0={A0,B0}, G1={B1} ----
    load_A(smem_base, 0, b, l0, gcol + 0);
    load_B(smem_base, 0, /*ks=*/0, /*cbase=*/0, ncol0);
    asm volatile("cp.async.commit_group;");
    load_B(smem_base, 1, /*ks=*/1, /*cbase=*/0, ncol0);
    asm volatile("cp.async.commit_group;");

    float acc[2][8][4];
#pragma unroll
    for (int u = 0; u < 2; ++u)
#pragma unroll
        for (int j = 0; j < 8; ++j)
#pragma unroll
            for (int q = 0; q < 4; ++q) acc[u][j][q] = 0.f;

    for (int s = 0; s < NSTAGES; ++s) {
        const int ks = s & 3;
        const uint32_t sA = smem_base + ((s >> 2) & 1) * A_BUF;
        const uint32_t sB = smem_base + OFF_B + (s % 3) * B_BUF;

        if (s == NSTAGES - 1) asm volatile("cp.async.wait_group 0;");
        else                  asm volatile("cp.async.wait_group 1;");
        __syncthreads();

        // Issue loads for stage s+2 right away:
        //  - B buffer (s+2)%3 was last consumed at stage s-1 (barrier above covers it).
        //  - A buffer flips only when (s+2)%4==0; its previous use ended at stage s-1 too.
        if (s < NSTAGES - 2) {
            const int s2 = s + 2;
            if ((s2 & 3) == 0)
                load_A(smem_base, (s2 >> 2) & 1, b, l0, gcol + (s2 >> 2) * 64);
            load_B(smem_base, s2 % 3, s2 & 3, (s2 >> 2) * 64, ncol0);
            asm volatile("cp.async.commit_group;");
        }

#pragma unroll
        for (int t = 0; t < 4; ++t) {
            uint32_t ah[2][4];
#pragma unroll
            for (int u = 0; u < 2; ++u) {
                int row = wm * 32 + u * 16 + (lid & 15) + ks;
                int lc  = t * 2 + (lid >> 4);
                uint32_t addr = sA + row * 128 + (((uint32_t)lc ^ (row & 7)) << 4);
                LDSM4(ah[u][0], ah[u][1], ah[u][2], ah[u][3], addr);
            }
            uint32_t bh[4][4];
#pragma unroll
            for (int j2 = 0; j2 < 4; ++j2) {
                int row = t * 16 + (lid & 15);
                int lc  = wn * 8 + j2 * 2 + (lid >> 4);
                uint32_t addr = sB + row * 256 + (((uint32_t)lc ^ (row & 7)) << 4);
                LDSM4T(bh[j2][0], bh[j2][1], bh[j2][2], bh[j2][3], addr);
            }
#pragma unroll
            for (int u = 0; u < 2; ++u)
#pragma unroll
                for (int j = 0; j < 8; ++j) {
                    int j2 = j >> 1, o = (j & 1) * 2;
                    MMA(acc[u][j], ah[u][0], ah[u][1], ah[u][2], ah[u][3],
                        bh[j2][o], bh[j2][o + 1]);
                }
        }
    }

    // ---- epilogue: acc regs -> out ----
#pragma unroll
    for (int u = 0; u < 2; ++u)
#pragma unroll
        for (int j = 0; j < 8; ++j) {
            int m0 = wm * 32 + u * 16 + (lid >> 2);
            int n  = wn * 64 + j * 8 + (lid & 3) * 2;
            float* p = out + (size_t)(b * L_ + l0 + m0) * D_ + ncol0 + n;
            *reinterpret_cast<float2*>(p) = make_float2(acc[u][j][0], acc[u][j][1]);
            *reinterpret_cast<float2*>(p + 8 * D_) = make_float2(acc[u][j][2], acc[u][j][3]);
        }
}

extern "C" void kernel_launch(void* const* d_in, const int* in_sizes, int n_in,
                              void* d_out, int out_size) {
    const float* x = (const float*)d_in[0];   // [4, 4096, 2048] fp32
    const float* w = (const float*)d_in[1];   // [4, 256, 2048] fp32
    float* out = (float*)d_out;               // [4, 4096, 2048] fp32

    // pre-convert fp32 -> fp16 (fused, one launch)
    cvt_kernel<<<(NX4 + NW4 + 255) / 256, 256>>>(x, w);

    cudaFuncSetAttribute(cc1d_mma_kernel, cudaFuncAttributeMaxDynamicSharedMemorySize, SMEM_TOTAL);
    // 2048 CTAs = 4 b x 8 g x 32 l-tiles x 2 n-tiles
    cc1d_mma_kernel<<<B_ * 8 * 32 * 2, NTHREADS, SMEM_TOTAL>>>(out);
}